// round 1
// baseline (speedup 1.0000x reference)
#include <cuda_runtime.h>
#include <cuda_bf16.h>
#include <mma.h>

using namespace nvcuda;

// ---------------- problem constants ----------------
#define BATCH   256
#define INSTRS  64
#define TOKENS  16
#define HID     256
#define EMB     256
#define FOURH   1024
#define KTOT    512          // E + H (token) or H + H (instr)
#define NTOK    (BATCH*INSTRS)   // 16384 token-level sequences

// ---------------- scratch (device globals; no allocs allowed) ----------------
__device__ float g_G[(size_t)NTOK * FOURH];      // gate pre-activations (64 MB, L2-resident)
__device__ float g_h_tok[(size_t)NTOK * HID];    // token-LSTM hidden  == instr_repr [B,I,H]
__device__ float g_c_tok[(size_t)NTOK * HID];
__device__ float g_h_ins[(size_t)BATCH * HID];
__device__ float g_c_ins[(size_t)BATCH * HID];

// ---------------- GEMM tile config ----------------
#define BM 128
#define BN 64
#define BK 32
#define LDS 36   // BK + 4 padding (multiple of 4 -> legal wmma ldm, 16B-aligned rows)

// G[n, j] = sum_k A[n,k] * W[j,k]
//   A[n, 0:256]   = (mode==0) ? embedding[tok[n,t]]      : h_tok[(n*64 + t)]   (x input)
//   A[n, 256:512] = (mode==0) ? h_tok[n]                 : h_ins[n]
//   W[j, 0:256]   = Wih[j], W[j, 256:512] = Whh[j]
__global__ void __launch_bounds__(256)
lstm_gemm(int mode, int t,
          const float* __restrict__ emb,
          const int*   __restrict__ tok,
          const float* __restrict__ Wih,
          const float* __restrict__ Whh)
{
    __shared__ float As[BM * LDS];
    __shared__ float Bs[BN * LDS];
    __shared__ const float* Arow[BM];

    const int tid = threadIdx.x;
    const int m0  = blockIdx.x * BM;
    const int n0  = blockIdx.y * BN;

    const float* hbase = (mode == 0) ? g_h_tok : g_h_ins;

    // per-row x-source pointers (fused embedding gather / time-slice select)
    for (int r = tid; r < BM; r += 256) {
        int n = m0 + r;
        const float* p;
        if (mode == 0) p = emb + (size_t)tok[n * TOKENS + t] * EMB;
        else           p = g_h_tok + ((size_t)n * INSTRS + t) * HID;
        Arow[r] = p;
    }

    wmma::fragment<wmma::accumulator, 16, 16, 8, float> cfrag[2][2];
#pragma unroll
    for (int mi = 0; mi < 2; ++mi)
#pragma unroll
        for (int ni = 0; ni < 2; ++ni)
            wmma::fill_fragment(cfrag[mi][ni], 0.0f);

    const int warp = tid >> 5;
    const int wm   = warp >> 1;   // 0..3  -> 32-row slice
    const int wn   = warp & 1;    // 0..1  -> 32-col slice

    for (int kt = 0; kt < KTOT; kt += BK) {
        __syncthreads();  // also covers Arow on first iteration

        // load A tile: BM x BK = 1024 float4, 4 per thread
#pragma unroll
        for (int i = tid; i < BM * BK / 4; i += 256) {
            int r  = i >> 3;            // 8 float4 per row
            int c4 = (i & 7) << 2;      // float col
            int kc = kt + c4;
            const float* src = (kc < 256) ? (Arow[r] + kc)
                                          : (hbase + (size_t)(m0 + r) * HID + (kc - 256));
            float4 v = *(const float4*)src;
            float* d = &As[r * LDS + c4];
            d[0] = wmma::__float_to_tf32(v.x);
            d[1] = wmma::__float_to_tf32(v.y);
            d[2] = wmma::__float_to_tf32(v.z);
            d[3] = wmma::__float_to_tf32(v.w);
        }
        // load B tile: BN x BK = 512 float4, 2 per thread
#pragma unroll
        for (int i = tid; i < BN * BK / 4; i += 256) {
            int r  = i >> 3;
            int c4 = (i & 7) << 2;
            int kc = kt + c4;
            const float* W   = (kc < 256) ? Wih : Whh;
            const float* src = W + (size_t)(n0 + r) * 256 + (kc & 255);
            float4 v = *(const float4*)src;
            float* d = &Bs[r * LDS + c4];
            d[0] = wmma::__float_to_tf32(v.x);
            d[1] = wmma::__float_to_tf32(v.y);
            d[2] = wmma::__float_to_tf32(v.z);
            d[3] = wmma::__float_to_tf32(v.w);
        }
        __syncthreads();

#pragma unroll
        for (int kk = 0; kk < BK; kk += 8) {
            wmma::fragment<wmma::matrix_a, 16, 16, 8, wmma::precision::tf32, wmma::row_major> a[2];
            wmma::fragment<wmma::matrix_b, 16, 16, 8, wmma::precision::tf32, wmma::col_major> b[2];
#pragma unroll
            for (int mi = 0; mi < 2; ++mi)
                wmma::load_matrix_sync(a[mi], &As[(wm * 32 + mi * 16) * LDS + kk], LDS);
#pragma unroll
            for (int ni = 0; ni < 2; ++ni)
                wmma::load_matrix_sync(b[ni], &Bs[(wn * 32 + ni * 16) * LDS + kk], LDS);
#pragma unroll
            for (int mi = 0; mi < 2; ++mi)
#pragma unroll
                for (int ni = 0; ni < 2; ++ni)
                    wmma::mma_sync(cfrag[mi][ni], a[mi], b[ni], cfrag[mi][ni]);
        }
    }

#pragma unroll
    for (int mi = 0; mi < 2; ++mi)
#pragma unroll
        for (int ni = 0; ni < 2; ++ni) {
            size_t row = (size_t)(m0 + wm * 32 + mi * 16);
            int    col = n0 + wn * 32 + ni * 16;
            wmma::store_matrix_sync(&g_G[row * FOURH + col], cfrag[mi][ni],
                                    FOURH, wmma::mem_row_major);
        }
}

// pointwise LSTM cell update with pack_padded masking (h,c frozen once t >= len)
__global__ void __launch_bounds__(256)
lstm_update(int mode, int t,
            const float* __restrict__ bias,
            const int*   __restrict__ len)
{
    int idx = blockIdx.x * 256 + threadIdx.x;
    int n = idx >> 8;
    int d = idx & 255;
    if (t >= len[n]) return;

    float* h = mode ? g_h_ins : g_h_tok;
    float* c = mode ? g_c_ins : g_c_tok;

    const float* g = g_G + (size_t)n * FOURH;
    float gi = g[d]       + bias[d];
    float gf = g[256 + d] + bias[256 + d];
    float gg = g[512 + d] + bias[512 + d];
    float go = g[768 + d] + bias[768 + d];

    float i_ = 1.0f / (1.0f + expf(-gi));
    float f_ = 1.0f / (1.0f + expf(-gf));
    float g_ = tanhf(gg);
    float o_ = 1.0f / (1.0f + expf(-go));

    float cn = f_ * c[idx] + i_ * g_;
    c[idx] = cn;
    h[idx] = o_ * tanhf(cn);
}

// zero all state (required every call: masked rows must read zeros; replays must be deterministic)
__global__ void __launch_bounds__(256) zero_state()
{
    int idx = blockIdx.x * 256 + threadIdx.x;   // grid covers NTOK*HID exactly
    g_h_tok[idx] = 0.0f;
    g_c_tok[idx] = 0.0f;
    if (idx < BATCH * HID) {
        g_h_ins[idx] = 0.0f;
        g_c_ins[idx] = 0.0f;
    }
}

// out[b] = dot(h_ins[b,:], linW) + linb
__global__ void __launch_bounds__(256)
final_linear(const float* __restrict__ linW,
             const float* __restrict__ linb,
             float* __restrict__ out)
{
    int b   = blockIdx.x;
    int tid = threadIdx.x;
    float v = g_h_ins[(size_t)b * HID + tid] * linW[tid];
#pragma unroll
    for (int o = 16; o > 0; o >>= 1) v += __shfl_down_sync(0xffffffffu, v, o);
    __shared__ float red[8];
    if ((tid & 31) == 0) red[tid >> 5] = v;
    __syncthreads();
    if (tid < 8) {
        float s = red[tid];
#pragma unroll
        for (int o = 4; o > 0; o >>= 1) s += __shfl_down_sync(0xffu, s, o);
        if (tid == 0) out[b] = s + linb[0];
    }
}

extern "C" void kernel_launch(void* const* d_in, const int* in_sizes, int n_in,
                              void* d_out, int out_size)
{
    const int*   blocks = (const int*)d_in[0];   // [256,64,16]
    const int*   ninstr = (const int*)d_in[1];   // [256]
    const int*   ntok   = (const int*)d_in[2];   // [256,64]
    const float* emb    = (const float*)d_in[3]; // [4096,256]
    const float* WihT   = (const float*)d_in[4]; // [1024,256]
    const float* WhhT   = (const float*)d_in[5];
    const float* bT     = (const float*)d_in[6];
    const float* WihI   = (const float*)d_in[7];
    const float* WhhI   = (const float*)d_in[8];
    const float* bI     = (const float*)d_in[9];
    const float* linW   = (const float*)d_in[10];
    const float* linb   = (const float*)d_in[11];
    float* out = (float*)d_out;

    (void)in_sizes; (void)n_in; (void)out_size;

    zero_state<<<NTOK * HID / 256, 256>>>();

    // ---- token-level LSTM: 16 steps over 16384 sequences ----
    for (int t = 0; t < TOKENS; ++t) {
        dim3 grid(NTOK / BM, FOURH / BN);                  // 128 x 16
        lstm_gemm<<<grid, 256>>>(0, t, emb, blocks, WihT, WhhT);
        lstm_update<<<NTOK * HID / 256, 256>>>(0, t, bT, ntok);
    }

    // ---- instruction-level LSTM: 64 steps over 256 sequences ----
    for (int s = 0; s < INSTRS; ++s) {
        dim3 grid(BATCH / BM, FOURH / BN);                 // 2 x 16
        lstm_gemm<<<grid, 256>>>(1, s, /*emb*/nullptr, /*tok*/nullptr, WihI, WhhI);
        lstm_update<<<BATCH * HID / 256, 256>>>(1, s, bI, ninstr);
    }

    final_linear<<<BATCH, 256>>>(linW, linb, out);
}

// round 4
// speedup vs baseline: 1.7447x; 1.7447x over previous
#include <cuda_runtime.h>
#include <cuda_bf16.h>
#include <mma.h>
#include <cstdint>

using namespace nvcuda;

// ---------------- problem constants ----------------
#define BATCH   256
#define INSTRS  64
#define TOKENS  16
#define HID     256
#define EMB     256
#define FOURH   1024
#define KTOT    512
#define NTOK    (BATCH*INSTRS)   // 16384

// ---------------- GEMM tile config ----------------
#define BM 128
#define BN 64
#define BK 32
#define LDS 36                   // BK + 4 pad (rows 144B, 16B aligned)
#define NK  (KTOT/BK)            // 16
#define CLD 68                   // epilogue Cs stride

// dynamic smem layout:
//  As: [2][BM*LDS] floats            (Cs [128][68] overlays As)
//  Bs: [2][BN*LDS] floats @ 9216 f
//  Aidx: int[128]          @ byte 55296
//  Arow: ptr[128]          @ byte 55808
#define SMEM_BYTES 56832

// ---------------- device state ----------------
// h is PING-PONGED by step parity: step t reads h[(t&1)^1], writes h[t&1].
// This removes the cross-block WAR race of the fused read+write kernel.
__device__ float g_h_tok[2][(size_t)NTOK * HID];
__device__ float g_c_tok[(size_t)NTOK * HID];
__device__ float g_h_ins[2][(size_t)BATCH * HID];
__device__ float g_c_ins[(size_t)BATCH * HID];
__device__ float g_instr_repr[(size_t)NTOK * HID];   // token-phase output (gathered)
__device__ int   g_perm_tok[NTOK];
__device__ int   g_cnt_tok[TOKENS];
__device__ int   g_perm_ins[BATCH];
__device__ int   g_cnt_ins[INSTRS];
// pre-rounded (RN tf32) operands
__device__ float g_emb_t[(size_t)4096 * EMB];
__device__ float g_W_tok[(size_t)FOURH * KTOT];   // [jp][512], gate-interleaved rows
__device__ float g_W_ins[(size_t)FOURH * KTOT];

__device__ __forceinline__ float tf32r(float x) {
    asm("cvt.rna.tf32.f32 %0, %0;" : "+f"(x));
    return x;
}

#define CP_ASYNC16(dst, src) \
    asm volatile("cp.async.cg.shared.global [%0], [%1], 16;" :: "r"(dst), "l"(src))
#define CP_COMMIT  asm volatile("cp.async.commit_group;")
#define CP_WAIT0   asm volatile("cp.async.wait_group 0;")

// Fused LSTM step: gate-interleaved GEMM + in-block cell update.
// h read/write use opposite parity buffers (race-free across blocks).
template<int MODE>
__global__ void __launch_bounds__(256)
fused_step(int t,
           const int*   __restrict__ tok,
           const float* __restrict__ bias,
           const int*   __restrict__ len_arr)
{
    const int cnt = (MODE == 0) ? g_cnt_tok[t] : g_cnt_ins[t];
    const int m0  = blockIdx.x * BM;
    if (m0 >= cnt) return;

    extern __shared__ float sm[];
    float*        As   = sm;
    float*        Bs   = sm + 2 * BM * LDS;
    int*          Aidx = (int*)((char*)sm + 55296);
    const float** Arow = (const float**)((char*)sm + 55808);
    float*        Cs   = sm;   // overlay

    const int n0  = blockIdx.y * BN;
    const int tid = threadIdx.x;
    const int wp  = t & 1;          // write parity
    const int rp  = wp ^ 1;         // read parity

    const int*   perm  = (MODE == 0) ? g_perm_tok : g_perm_ins;
    const float* hbase = (MODE == 0) ? g_h_tok[rp] : g_h_ins[rp];
    const float* Wbuf  = (MODE == 0) ? g_W_tok : g_W_ins;

    for (int r = tid; r < BM; r += 256) {
        int n = perm[m0 + r];
        Aidx[r] = n;
        if (MODE == 0)
            Arow[r] = g_emb_t + (size_t)__ldg(&tok[n * TOKENS + t]) * EMB;
        else
            Arow[r] = g_instr_repr + ((size_t)n * INSTRS + t) * HID;
    }
    __syncthreads();

    auto issue = [&](int kt, int buf) {
        float* Ad = As + buf * BM * LDS;
#pragma unroll
        for (int i = 0; i < 4; ++i) {
            int c  = tid + i * 256;
            int r  = c >> 3;
            int c4 = (c & 7) << 2;
            const float* src = (kt < 8)
                ? Arow[r] + kt * BK + c4
                : hbase + (size_t)Aidx[r] * HID + (kt - 8) * BK + c4;
            uint32_t dst = (uint32_t)__cvta_generic_to_shared(Ad + r * LDS + c4);
            CP_ASYNC16(dst, src);
        }
        float* Bd = Bs + buf * BN * LDS;
#pragma unroll
        for (int i = 0; i < 2; ++i) {
            int c  = tid + i * 256;
            int r  = c >> 3;
            int c4 = (c & 7) << 2;
            const float* src = Wbuf + (size_t)(n0 + r) * KTOT + kt * BK + c4;
            uint32_t dst = (uint32_t)__cvta_generic_to_shared(Bd + r * LDS + c4);
            CP_ASYNC16(dst, src);
        }
        CP_COMMIT;
    };

    wmma::fragment<wmma::accumulator, 16, 16, 8, float> cf[2][2];
#pragma unroll
    for (int mi = 0; mi < 2; ++mi)
#pragma unroll
        for (int ni = 0; ni < 2; ++ni)
            wmma::fill_fragment(cf[mi][ni], 0.0f);

    const int warp = tid >> 5;
    const int wm   = warp >> 1;
    const int wn   = warp & 1;

    issue(0, 0);
    for (int kt = 0; kt < NK; ++kt) {
        CP_WAIT0;
        __syncthreads();
        if (kt + 1 < NK) issue(kt + 1, (kt + 1) & 1);
        const float* Ab = As + (kt & 1) * BM * LDS;
        const float* Bb = Bs + (kt & 1) * BN * LDS;
#pragma unroll
        for (int kk = 0; kk < BK; kk += 8) {
            wmma::fragment<wmma::matrix_a, 16, 16, 8, wmma::precision::tf32, wmma::row_major> a[2];
            wmma::fragment<wmma::matrix_b, 16, 16, 8, wmma::precision::tf32, wmma::col_major> b[2];
#pragma unroll
            for (int mi = 0; mi < 2; ++mi)
                wmma::load_matrix_sync(a[mi], Ab + (wm * 32 + mi * 16) * LDS + kk, LDS);
#pragma unroll
            for (int ni = 0; ni < 2; ++ni)
                wmma::load_matrix_sync(b[ni], Bb + (wn * 32 + ni * 16) * LDS + kk, LDS);
#pragma unroll
            for (int mi = 0; mi < 2; ++mi)
#pragma unroll
                for (int ni = 0; ni < 2; ++ni)
                    wmma::mma_sync(cf[mi][ni], a[mi], b[ni], cf[mi][ni]);
        }
    }

    // ---- epilogue: stage gates, apply cell update ----
    __syncthreads();
#pragma unroll
    for (int mi = 0; mi < 2; ++mi)
#pragma unroll
        for (int ni = 0; ni < 2; ++ni)
            wmma::store_matrix_sync(&Cs[(wm * 32 + mi * 16) * CLD + wn * 32 + ni * 16],
                                    cf[mi][ni], CLD, wmma::mem_row_major);
    __syncthreads();

    {
        int r = tid >> 1;
        int n = Aidx[r];
        int L = __ldg(&len_arr[n]);
        if (t < L) {
            float* hp = (MODE == 0) ? g_h_tok[wp] : g_h_ins[wp];
            float* cp = (MODE == 0) ? g_c_tok : g_c_ins;
            int dg0 = (n0 >> 2) + (tid & 1) * 8;
#pragma unroll
            for (int i = 0; i < 8; ++i) {
                int dl = (tid & 1) * 8 + i;
                int dg = dg0 + i;
                float gi = Cs[r * CLD + dl * 4 + 0] + __ldg(&bias[dg]);
                float gf = Cs[r * CLD + dl * 4 + 1] + __ldg(&bias[256 + dg]);
                float gg = Cs[r * CLD + dl * 4 + 2] + __ldg(&bias[512 + dg]);
                float go = Cs[r * CLD + dl * 4 + 3] + __ldg(&bias[768 + dg]);
                float i_ = 1.0f / (1.0f + expf(-gi));
                float f_ = 1.0f / (1.0f + expf(-gf));
                float g_ = tanhf(gg);
                float o_ = 1.0f / (1.0f + expf(-go));
                size_t idx = (size_t)n * HID + dg;
                float cn = f_ * cp[idx] + i_ * g_;
                cp[idx] = cn;
                hp[idx] = tf32r(o_ * tanhf(cn));   // RN tf32: exact MMA operand next step
            }
        }
    }
}

// gather final token-phase h from the parity buffer of each row's last step
__global__ void __launch_bounds__(256)
gather_tok(const int* __restrict__ ntok)
{
    int idx = blockIdx.x * 256 + threadIdx.x;   // over NTOK*HID
    int n = idx >> 8;
    int L = ntok[n];
    g_instr_repr[idx] = (L > 0) ? g_h_tok[(L - 1) & 1][idx] : 0.0f;
}

// pre-round weights into gate-interleaved [jp][512] (RN tf32)
__global__ void __launch_bounds__(256)
prep_weights(const float* __restrict__ WihT, const float* __restrict__ WhhT,
             const float* __restrict__ WihI, const float* __restrict__ WhhI)
{
    int idx = blockIdx.x * 256 + threadIdx.x;   // over 1024*512
    int jp = idx >> 9;
    int k  = idx & 511;
    int j  = (jp & 3) * 256 + (jp >> 2);        // de-interleave: gate*256 + d
    float v = (k < 256) ? WihT[j * 256 + k] : WhhT[j * 256 + (k - 256)];
    g_W_tok[idx] = tf32r(v);
    float u = (k < 256) ? WihI[j * 256 + k] : WhhI[j * 256 + (k - 256)];
    g_W_ins[idx] = tf32r(u);
}

__global__ void __launch_bounds__(256)
prep_emb(const float* __restrict__ emb)
{
    int idx = blockIdx.x * 256 + threadIdx.x;   // over 4096*256
    g_emb_t[idx] = tf32r(emb[idx]);
}

// counting sort by length (descending) + active-count table
__global__ void build_perm(const int* __restrict__ ntok,
                           const int* __restrict__ ninstr)
{
    __shared__ int hist[65];
    __shared__ int off[65];
    if (blockIdx.x == 0) {
        for (int i = threadIdx.x; i < 17; i += blockDim.x) hist[i] = 0;
        __syncthreads();
        for (int i = threadIdx.x; i < NTOK; i += blockDim.x)
            atomicAdd(&hist[ntok[i]], 1);
        __syncthreads();
        if (threadIdx.x == 0) {
            int acc = 0;
            for (int l = 16; l >= 0; --l) { off[l] = acc; acc += hist[l]; }
            for (int t = 0; t < TOKENS; ++t) g_cnt_tok[t] = off[t];
        }
        __syncthreads();
        for (int i = threadIdx.x; i < NTOK; i += blockDim.x) {
            int p = atomicAdd(&off[ntok[i]], 1);
            g_perm_tok[p] = i;
        }
    } else {
        for (int i = threadIdx.x; i < 65; i += blockDim.x) hist[i] = 0;
        __syncthreads();
        for (int i = threadIdx.x; i < BATCH; i += blockDim.x)
            atomicAdd(&hist[ninstr[i]], 1);
        __syncthreads();
        if (threadIdx.x == 0) {
            int acc = 0;
            for (int l = 64; l >= 0; --l) { off[l] = acc; acc += hist[l]; }
            for (int s = 0; s < INSTRS; ++s) g_cnt_ins[s] = off[s];
        }
        __syncthreads();
        for (int i = threadIdx.x; i < BATCH; i += blockDim.x) {
            int p = atomicAdd(&off[ninstr[i]], 1);
            g_perm_ins[p] = i;
        }
    }
}

__global__ void __launch_bounds__(256) zero_state()
{
    int idx = blockIdx.x * 256 + threadIdx.x;   // grid covers NTOK*HID
    g_h_tok[0][idx] = 0.0f;
    g_h_tok[1][idx] = 0.0f;
    g_c_tok[idx]    = 0.0f;
    if (idx < BATCH * HID) {
        g_h_ins[0][idx] = 0.0f;
        g_h_ins[1][idx] = 0.0f;
        g_c_ins[idx]    = 0.0f;
    }
}

__global__ void __launch_bounds__(256)
final_linear(const int* __restrict__ ninstr,
             const float* __restrict__ linW,
             const float* __restrict__ linb,
             float* __restrict__ out)
{
    int b = blockIdx.x, tid = threadIdx.x;
    int L = ninstr[b];
    float h = (L > 0) ? g_h_ins[(L - 1) & 1][(size_t)b * HID + tid] : 0.0f;
    float v = h * linW[tid];
#pragma unroll
    for (int o = 16; o > 0; o >>= 1) v += __shfl_down_sync(0xffffffffu, v, o);
    __shared__ float red[8];
    if ((tid & 31) == 0) red[tid >> 5] = v;
    __syncthreads();
    if (tid < 8) {
        float s = red[tid];
#pragma unroll
        for (int o = 4; o > 0; o >>= 1) s += __shfl_down_sync(0xffu, s, o);
        if (tid == 0) out[b] = s + linb[0];
    }
}

extern "C" void kernel_launch(void* const* d_in, const int* in_sizes, int n_in,
                              void* d_out, int out_size)
{
    const int*   blocks = (const int*)d_in[0];
    const int*   ninstr = (const int*)d_in[1];
    const int*   ntok   = (const int*)d_in[2];
    const float* emb    = (const float*)d_in[3];
    const float* WihT   = (const float*)d_in[4];
    const float* WhhT   = (const float*)d_in[5];
    const float* bT     = (const float*)d_in[6];
    const float* WihI   = (const float*)d_in[7];
    const float* WhhI   = (const float*)d_in[8];
    const float* bI     = (const float*)d_in[9];
    const float* linW   = (const float*)d_in[10];
    const float* linb   = (const float*)d_in[11];
    float* out = (float*)d_out;
    (void)in_sizes; (void)n_in; (void)out_size;

    cudaFuncSetAttribute(fused_step<0>, cudaFuncAttributeMaxDynamicSharedMemorySize, SMEM_BYTES);
    cudaFuncSetAttribute(fused_step<1>, cudaFuncAttributeMaxDynamicSharedMemorySize, SMEM_BYTES);

    zero_state<<<NTOK * HID / 256, 256>>>();
    build_perm<<<2, 512>>>(ntok, ninstr);
    prep_weights<<<FOURH * KTOT / 256, 256>>>(WihT, WhhT, WihI, WhhI);
    prep_emb<<<4096 * EMB / 256, 256>>>(emb);

    for (int t = 0; t < TOKENS; ++t) {
        dim3 grid(NTOK / BM, FOURH / BN);          // 128 x 16, blocks self-trim
        fused_step<0><<<grid, 256, SMEM_BYTES>>>(t, blocks, bT, ntok);
    }
    gather_tok<<<NTOK * HID / 256, 256>>>(ntok);
    for (int s = 0; s < INSTRS; ++s) {
        dim3 grid(BATCH / BM, FOURH / BN);         // 2 x 16
        fused_step<1><<<grid, 256, SMEM_BYTES>>>(s, nullptr, bI, ninstr);
    }
    final_linear<<<BATCH, 256>>>(ninstr, linW, linb, out);
}

// round 5
// speedup vs baseline: 4.2326x; 2.4259x over previous
#include <cuda_runtime.h>
#include <cuda_fp16.h>
#include <mma.h>
#include <cstdint>

using namespace nvcuda;

// ---------------- problem constants ----------------
#define BATCH   256
#define INSTRS  64
#define TOKENS  16
#define HID     256
#define EMB     256
#define FOURH   1024
#define KTOT    512
#define NTOK    (BATCH*INSTRS)   // 16384

// ---------------- GEMM tile config (fp16 m16n16k16) ----------------
#define BM 128
#define BN 64
#define BK 64
#define LDSH 72                  // BK + 8 pad (half elems; rows 144B, 16B aligned)
#define NK  (KTOT/BK)            // 8
#define CLD 68                   // epilogue Cs stride (floats)

// dynamic smem layout (bytes):
//  As: [2][BM*LDSH] half = 36864         (Cs float[128][68]=34816 overlays)
//  Bs: [2][BN*LDSH] half @ 36864, 18432
//  Aidx: int[128]        @ 55296
//  Arow: ptr[128]        @ 55808
#define SMEM_BYTES 56832

// ---------------- device state ----------------
// h ping-ponged by step parity: step t reads h[(t&1)^1], writes h[t&1].
__device__ __half g_h_tok[2][(size_t)NTOK * HID];
__device__ float  g_c_tok[(size_t)NTOK * HID];
__device__ __half g_h_ins[2][(size_t)BATCH * HID];
__device__ float  g_c_ins[(size_t)BATCH * HID];
__device__ __half g_instr_repr[(size_t)NTOK * HID];
__device__ int    g_perm_tok[NTOK];
__device__ int    g_cnt_tok[TOKENS];
__device__ int    g_perm_ins[BATCH];
__device__ int    g_cnt_ins[INSTRS];
// pre-converted fp16 operands
__device__ __half g_emb_h[(size_t)4096 * EMB];
__device__ __half g_W_tok[(size_t)FOURH * KTOT];   // [jp][512], gate-interleaved rows
__device__ __half g_W_ins[(size_t)FOURH * KTOT];

#define CP_ASYNC16(dst, src) \
    asm volatile("cp.async.cg.shared.global [%0], [%1], 16;" :: "r"(dst), "l"(src))
#define CP_COMMIT  asm volatile("cp.async.commit_group;")
#define CP_WAIT0   asm volatile("cp.async.wait_group 0;")

// Fused LSTM step: gate-interleaved fp16 GEMM + in-block cell update.
template<int MODE>
__global__ void __launch_bounds__(256)
fused_step(int t,
           const int*   __restrict__ tok,
           const float* __restrict__ bias,
           const int*   __restrict__ len_arr)
{
    const int cnt = (MODE == 0) ? g_cnt_tok[t] : g_cnt_ins[t];
    const int m0  = blockIdx.x * BM;
    if (m0 >= cnt) return;

    extern __shared__ char smraw[];
    __half*        As   = (__half*)smraw;                    // [2][BM*LDSH]
    __half*        Bs   = (__half*)(smraw + 36864);          // [2][BN*LDSH]
    int*           Aidx = (int*)(smraw + 55296);
    const __half** Arow = (const __half**)(smraw + 55808);
    float*         Cs   = (float*)smraw;                     // overlay

    const int n0  = blockIdx.y * BN;
    const int tid = threadIdx.x;
    const int wp  = t & 1;
    const int rp  = wp ^ 1;

    const int*    perm  = (MODE == 0) ? g_perm_tok : g_perm_ins;
    const __half* hbase = (MODE == 0) ? g_h_tok[rp] : g_h_ins[rp];
    const __half* Wbuf  = (MODE == 0) ? g_W_tok : g_W_ins;

    for (int r = tid; r < BM; r += 256) {
        int n = perm[m0 + r];
        Aidx[r] = n;
        if (MODE == 0)
            Arow[r] = g_emb_h + (size_t)__ldg(&tok[n * TOKENS + t]) * EMB;
        else
            Arow[r] = g_instr_repr + ((size_t)n * INSTRS + t) * HID;
    }
    __syncthreads();

    auto issue = [&](int kt, int buf) {
        __half* Ad = As + buf * BM * LDSH;
        // A tile: 128x64 half = 1024 x 16B chunks, 4 per thread
#pragma unroll
        for (int i = 0; i < 4; ++i) {
            int c  = tid + i * 256;
            int r  = c >> 3;             // 8 chunks per row
            int c8 = (c & 7) << 3;       // half index
            const __half* src = (kt < 4)
                ? Arow[r] + kt * BK + c8
                : hbase + (size_t)Aidx[r] * HID + (kt - 4) * BK + c8;
            uint32_t dst = (uint32_t)__cvta_generic_to_shared(Ad + r * LDSH + c8);
            CP_ASYNC16(dst, src);
        }
        __half* Bd = Bs + buf * BN * LDSH;
        // B tile: 64x64 half = 512 chunks, 2 per thread
#pragma unroll
        for (int i = 0; i < 2; ++i) {
            int c  = tid + i * 256;
            int r  = c >> 3;
            int c8 = (c & 7) << 3;
            const __half* src = Wbuf + (size_t)(n0 + r) * KTOT + kt * BK + c8;
            uint32_t dst = (uint32_t)__cvta_generic_to_shared(Bd + r * LDSH + c8);
            CP_ASYNC16(dst, src);
        }
        CP_COMMIT;
    };

    wmma::fragment<wmma::accumulator, 16, 16, 16, float> cf[2][2];
#pragma unroll
    for (int mi = 0; mi < 2; ++mi)
#pragma unroll
        for (int ni = 0; ni < 2; ++ni)
            wmma::fill_fragment(cf[mi][ni], 0.0f);

    const int warp = tid >> 5;
    const int wm   = warp >> 1;   // 0..3: 32-row slice
    const int wn   = warp & 1;    // 0..1: 32-col slice

    issue(0, 0);
    for (int kt = 0; kt < NK; ++kt) {
        CP_WAIT0;
        __syncthreads();
        if (kt + 1 < NK) issue(kt + 1, (kt + 1) & 1);
        const __half* Ab = As + (kt & 1) * BM * LDSH;
        const __half* Bb = Bs + (kt & 1) * BN * LDSH;
#pragma unroll
        for (int kk = 0; kk < BK; kk += 16) {
            wmma::fragment<wmma::matrix_a, 16, 16, 16, __half, wmma::row_major> a[2];
            wmma::fragment<wmma::matrix_b, 16, 16, 16, __half, wmma::col_major> b[2];
#pragma unroll
            for (int mi = 0; mi < 2; ++mi)
                wmma::load_matrix_sync(a[mi], Ab + (wm * 32 + mi * 16) * LDSH + kk, LDSH);
#pragma unroll
            for (int ni = 0; ni < 2; ++ni)
                wmma::load_matrix_sync(b[ni], Bb + (wn * 32 + ni * 16) * LDSH + kk, LDSH);
#pragma unroll
            for (int mi = 0; mi < 2; ++mi)
#pragma unroll
                for (int ni = 0; ni < 2; ++ni)
                    wmma::mma_sync(cf[mi][ni], a[mi], b[ni], cf[mi][ni]);
        }
    }

    // ---- epilogue: stage gates, apply cell update ----
    __syncthreads();
#pragma unroll
    for (int mi = 0; mi < 2; ++mi)
#pragma unroll
        for (int ni = 0; ni < 2; ++ni)
            wmma::store_matrix_sync(&Cs[(wm * 32 + mi * 16) * CLD + wn * 32 + ni * 16],
                                    cf[mi][ni], CLD, wmma::mem_row_major);
    __syncthreads();

    {
        int r = tid >> 1;
        int n = Aidx[r];
        int L = __ldg(&len_arr[n]);
        if (t < L) {
            __half* hp = (MODE == 0) ? g_h_tok[wp] : g_h_ins[wp];
            float*  cp = (MODE == 0) ? g_c_tok : g_c_ins;
            int dg0 = (n0 >> 2) + (tid & 1) * 8;
#pragma unroll
            for (int i = 0; i < 8; ++i) {
                int dl = (tid & 1) * 8 + i;
                int dg = dg0 + i;
                float gi = Cs[r * CLD + dl * 4 + 0] + __ldg(&bias[dg]);
                float gf = Cs[r * CLD + dl * 4 + 1] + __ldg(&bias[256 + dg]);
                float gg = Cs[r * CLD + dl * 4 + 2] + __ldg(&bias[512 + dg]);
                float go = Cs[r * CLD + dl * 4 + 3] + __ldg(&bias[768 + dg]);
                float i_ = 1.0f / (1.0f + expf(-gi));
                float f_ = 1.0f / (1.0f + expf(-gf));
                float g_ = tanhf(gg);
                float o_ = 1.0f / (1.0f + expf(-go));
                size_t idx = (size_t)n * HID + dg;
                float cn = f_ * cp[idx] + i_ * g_;
                cp[idx] = cn;
                hp[idx] = __float2half_rn(o_ * tanhf(cn));
            }
        }
    }
}

// gather final token-phase h from the parity buffer of each row's last step
__global__ void __launch_bounds__(256)
gather_tok(const int* __restrict__ ntok)
{
    int idx = blockIdx.x * 256 + threadIdx.x;   // over NTOK*HID
    int n = idx >> 8;
    int L = ntok[n];
    g_instr_repr[idx] = (L > 0) ? g_h_tok[(L - 1) & 1][idx] : __half(0.0f);
}

// convert weights into gate-interleaved fp16 [jp][512]
__global__ void __launch_bounds__(256)
prep_weights(const float* __restrict__ WihT, const float* __restrict__ WhhT,
             const float* __restrict__ WihI, const float* __restrict__ WhhI)
{
    int idx = blockIdx.x * 256 + threadIdx.x;   // over 1024*512
    int jp = idx >> 9;
    int k  = idx & 511;
    int j  = (jp & 3) * 256 + (jp >> 2);        // gate*256 + d
    float v = (k < 256) ? WihT[j * 256 + k] : WhhT[j * 256 + (k - 256)];
    g_W_tok[idx] = __float2half_rn(v);
    float u = (k < 256) ? WihI[j * 256 + k] : WhhI[j * 256 + (k - 256)];
    g_W_ins[idx] = __float2half_rn(u);
}

__global__ void __launch_bounds__(256)
prep_emb(const float* __restrict__ emb)
{
    int idx = blockIdx.x * 256 + threadIdx.x;   // over 4096*256
    g_emb_h[idx] = __float2half_rn(emb[idx]);
}

// counting sort by length (descending) + active-count table
__global__ void build_perm(const int* __restrict__ ntok,
                           const int* __restrict__ ninstr)
{
    __shared__ int hist[65];
    __shared__ int off[65];
    if (blockIdx.x == 0) {
        for (int i = threadIdx.x; i < 17; i += blockDim.x) hist[i] = 0;
        __syncthreads();
        for (int i = threadIdx.x; i < NTOK; i += blockDim.x)
            atomicAdd(&hist[ntok[i]], 1);
        __syncthreads();
        if (threadIdx.x == 0) {
            int acc = 0;
            for (int l = 16; l >= 0; --l) { off[l] = acc; acc += hist[l]; }
            for (int t = 0; t < TOKENS; ++t) g_cnt_tok[t] = off[t];
        }
        __syncthreads();
        for (int i = threadIdx.x; i < NTOK; i += blockDim.x) {
            int p = atomicAdd(&off[ntok[i]], 1);
            g_perm_tok[p] = i;
        }
    } else {
        for (int i = threadIdx.x; i < 65; i += blockDim.x) hist[i] = 0;
        __syncthreads();
        for (int i = threadIdx.x; i < BATCH; i += blockDim.x)
            atomicAdd(&hist[ninstr[i]], 1);
        __syncthreads();
        if (threadIdx.x == 0) {
            int acc = 0;
            for (int l = 64; l >= 0; --l) { off[l] = acc; acc += hist[l]; }
            for (int s = 0; s < INSTRS; ++s) g_cnt_ins[s] = off[s];
        }
        __syncthreads();
        for (int i = threadIdx.x; i < BATCH; i += blockDim.x) {
            int p = atomicAdd(&off[ninstr[i]], 1);
            g_perm_ins[p] = i;
        }
    }
}

__global__ void __launch_bounds__(256) zero_state()
{
    int idx = blockIdx.x * 256 + threadIdx.x;   // grid covers NTOK*HID
    g_h_tok[0][idx] = __half(0.0f);
    g_h_tok[1][idx] = __half(0.0f);
    g_c_tok[idx]    = 0.0f;
    if (idx < BATCH * HID) {
        g_h_ins[0][idx] = __half(0.0f);
        g_h_ins[1][idx] = __half(0.0f);
        g_c_ins[idx]    = 0.0f;
    }
}

__global__ void __launch_bounds__(256)
final_linear(const int* __restrict__ ninstr,
             const float* __restrict__ linW,
             const float* __restrict__ linb,
             float* __restrict__ out)
{
    int b = blockIdx.x, tid = threadIdx.x;
    int L = ninstr[b];
    float h = (L > 0) ? __half2float(g_h_ins[(L - 1) & 1][(size_t)b * HID + tid]) : 0.0f;
    float v = h * linW[tid];
#pragma unroll
    for (int o = 16; o > 0; o >>= 1) v += __shfl_down_sync(0xffffffffu, v, o);
    __shared__ float red[8];
    if ((tid & 31) == 0) red[tid >> 5] = v;
    __syncthreads();
    if (tid < 8) {
        float s = red[tid];
#pragma unroll
        for (int o = 4; o > 0; o >>= 1) s += __shfl_down_sync(0xffu, s, o);
        if (tid == 0) out[b] = s + linb[0];
    }
}

extern "C" void kernel_launch(void* const* d_in, const int* in_sizes, int n_in,
                              void* d_out, int out_size)
{
    const int*   blocks = (const int*)d_in[0];
    const int*   ninstr = (const int*)d_in[1];
    const int*   ntok   = (const int*)d_in[2];
    const float* emb    = (const float*)d_in[3];
    const float* WihT   = (const float*)d_in[4];
    const float* WhhT   = (const float*)d_in[5];
    const float* bT     = (const float*)d_in[6];
    const float* WihI   = (const float*)d_in[7];
    const float* WhhI   = (const float*)d_in[8];
    const float* bI     = (const float*)d_in[9];
    const float* linW   = (const float*)d_in[10];
    const float* linb   = (const float*)d_in[11];
    float* out = (float*)d_out;
    (void)in_sizes; (void)n_in; (void)out_size;

    cudaFuncSetAttribute(fused_step<0>, cudaFuncAttributeMaxDynamicSharedMemorySize, SMEM_BYTES);
    cudaFuncSetAttribute(fused_step<1>, cudaFuncAttributeMaxDynamicSharedMemorySize, SMEM_BYTES);

    zero_state<<<NTOK * HID / 256, 256>>>();
    build_perm<<<2, 512>>>(ntok, ninstr);
    prep_weights<<<FOURH * KTOT / 256, 256>>>(WihT, WhhT, WihI, WhhI);
    prep_emb<<<4096 * EMB / 256, 256>>>(emb);

    for (int t = 0; t < TOKENS; ++t) {
        dim3 grid(NTOK / BM, FOURH / BN);          // 128 x 16, blocks self-trim
        fused_step<0><<<grid, 256, SMEM_BYTES>>>(t, blocks, bT, ntok);
    }
    gather_tok<<<NTOK * HID / 256, 256>>>(ntok);
    for (int s = 0; s < INSTRS; ++s) {
        dim3 grid(BATCH / BM, FOURH / BN);         // 2 x 16
        fused_step<1><<<grid, 256, SMEM_BYTES>>>(s, nullptr, bI, ninstr);
    }
    final_linear<<<BATCH, 256>>>(ninstr, linW, linb, out);
}